// round 8
// baseline (speedup 1.0000x reference)
#include <cuda_runtime.h>
#include <cuda_bf16.h>
#include <math.h>

#define T 512
#define B 128
#define D 256
#define H 256

// Scratch for precomputed input projections, one per direction: [T*B, H]
__device__ float g_xw[2][(size_t)T * B * H];

typedef unsigned long long u64;
typedef unsigned int u32;

__device__ __forceinline__ u64 pk2(float lo, float hi) {
    u64 r; asm("mov.b64 %0, {%1, %2};" : "=l"(r) : "f"(lo), "f"(hi)); return r;
}
__device__ __forceinline__ void upk2(float& lo, float& hi, u64 v) {
    asm("mov.b64 {%0, %1}, %2;" : "=f"(lo), "=f"(hi) : "l"(v));
}
__device__ __forceinline__ void ffma2(u64& acc, u64 a, u64 b) {
    asm("fma.rn.f32x2 %0, %1, %2, %3;" : "=l"(acc) : "l"(a), "l"(b), "l"(acc));
}
__device__ __forceinline__ float tanh_fast(float x) {
    float y; asm("tanh.approx.f32 %0, %1;" : "=f"(y) : "f"(x)); return y;
}
// word = (bf16 w_k in low 16, bf16 w_{k+1} in high 16)
// -> u64 fp32 pair (w_k, w_{k+1}); bf16->fp32 expansion is exact.
__device__ __forceinline__ u64 bfpair(u32 w) {
    u64 r;
    asm("{ .reg .b32 lo, hi;\n"
        "  shl.b32 lo, %1, 16;\n"
        "  and.b32 hi, %1, 0xffff0000;\n"
        "  mov.b64 %0, {lo, hi}; }" : "=l"(r) : "r"(w));
    return r;
}

// ---------------------------------------------------------------------------
// Kernel 1: xw[dir] = inputs @ W_xh[dir] + b[dir]   (FFMA2 inner product)
// ---------------------------------------------------------------------------
#define BM 64
#define BN 128
#define BK 16

__global__ __launch_bounds__(256) void proj_kernel(
    const float* __restrict__ inp,
    const float* __restrict__ Wf, const float* __restrict__ bfp,
    const float* __restrict__ Wb, const float* __restrict__ bbp)
{
    const int dir = blockIdx.z;
    const float* __restrict__ Wx   = dir ? Wb : Wf;
    const float* __restrict__ bias = dir ? bbp : bfp;
    float* __restrict__ out = g_xw[dir];

    __shared__ float As[BK][BM + 4];
    __shared__ float Bs[BK][BN];

    const int m0 = blockIdx.x * BM;
    const int n0 = blockIdx.y * BN;

    const int tid = threadIdx.x;
    const int tx  = tid & 31;
    const int ty  = tid >> 5;

    const int am = tid >> 2;
    const int a4 = tid & 3;
    const int bn = tid & 31;
    const int bk = tid >> 5;

    u64 acc2[4][4];
    #pragma unroll
    for (int p = 0; p < 4; p++)
        #pragma unroll
        for (int c = 0; c < 4; c++) acc2[p][c] = 0ull;

    float bv[4];
    #pragma unroll
    for (int c = 0; c < 4; c++) bv[c] = bias[n0 + tx * 4 + c];

    for (int k0 = 0; k0 < D; k0 += BK) {
        {
            float4 v = *(const float4*)&inp[(size_t)(m0 + am) * D + k0 + a4 * 4];
            As[a4 * 4 + 0][am] = v.x;
            As[a4 * 4 + 1][am] = v.y;
            As[a4 * 4 + 2][am] = v.z;
            As[a4 * 4 + 3][am] = v.w;
        }
        {
            float4 v0 = *(const float4*)&Wx[(size_t)(k0 + bk) * H + n0 + bn * 4];
            float4 v1 = *(const float4*)&Wx[(size_t)(k0 + bk + 8) * H + n0 + bn * 4];
            *(float4*)&Bs[bk][bn * 4]     = v0;
            *(float4*)&Bs[bk + 8][bn * 4] = v1;
        }
        __syncthreads();

        #pragma unroll
        for (int kk = 0; kk < BK; kk++) {
            ulonglong2 ap0 = *(const ulonglong2*)&As[kk][ty * 8];
            ulonglong2 ap1 = *(const ulonglong2*)&As[kk][ty * 8 + 4];
            float4 bq = *(const float4*)&Bs[kk][tx * 4];
            u64 bb[4];
            bb[0] = pk2(bq.x, bq.x);
            bb[1] = pk2(bq.y, bq.y);
            bb[2] = pk2(bq.z, bq.z);
            bb[3] = pk2(bq.w, bq.w);
            #pragma unroll
            for (int c = 0; c < 4; c++) {
                ffma2(acc2[0][c], ap0.x, bb[c]);
                ffma2(acc2[1][c], ap0.y, bb[c]);
                ffma2(acc2[2][c], ap1.x, bb[c]);
                ffma2(acc2[3][c], ap1.y, bb[c]);
            }
        }
        __syncthreads();
    }

    #pragma unroll
    for (int p = 0; p < 4; p++) {
        float lo[4], hi[4];
        #pragma unroll
        for (int c = 0; c < 4; c++) upk2(lo[c], hi[c], acc2[p][c]);
        float4 v0 = make_float4(lo[0] + bv[0], lo[1] + bv[1], lo[2] + bv[2], lo[3] + bv[3]);
        float4 v1 = make_float4(hi[0] + bv[0], hi[1] + bv[1], hi[2] + bv[2], hi[3] + bv[3]);
        *(float4*)&out[(size_t)(m0 + ty * 8 + 2 * p)     * H + n0 + tx * 4] = v0;
        *(float4*)&out[(size_t)(m0 + ty * 8 + 2 * p + 1) * H + n0 + tx * 4] = v1;
    }
}

// ---------------------------------------------------------------------------
// Kernel 2: recurrent scan, persistent blocks (128 blocks, 1/SM, 512 thr).
// Split-K: thread (j = tid&255, kh = tid>>8) accumulates k in
// [kh*128, kh*128+128) for output column j, holding that half of W_hh column j
// as bf16 in 64 registers. kh=1 threads deposit partials in smem; kh=0 threads
// finalize (add x + partial, tanh), publish h (double-buffered), write output.
// 16 warps/SM (4 per SMSP) hide the rt-2 FFMA2/ALU streams and LDS latency.
// ---------------------------------------------------------------------------
#define NKH 16   // uint4 words per thread (16 * 8 = 128 k values)

__global__ __launch_bounds__(512, 1) void scan_kernel(
    const float* __restrict__ Whh_f,
    const float* __restrict__ Whh_b,
    float* __restrict__ out)
{
    __shared__ float hbuf[2][2][H];   // [phase][row][col]
    __shared__ float psum[2][H];      // kh=1 partials, [row][col]

    const int blk  = blockIdx.x;      // 0..127
    const int dir  = blk >> 6;
    const int brow = (blk & 63) * 2;
    const float* __restrict__ Whh = dir ? Whh_b : Whh_f;
    const float* __restrict__ xw  = g_xw[dir];

    const int j  = threadIdx.x & 255;   // output column
    const int kh = threadIdx.x >> 8;    // k-half: 0 or 1
    const int kb = kh << 7;             // k base: 0 or 128

    // ---- load this thread's half of W column j (bf16-packed, 64 regs)
    uint4 wreg[NKH];
    #pragma unroll
    for (int k8 = 0; k8 < NKH; k8++) {
        u32 wrd[4];
        #pragma unroll
        for (int q = 0; q < 4; q++) {
            float w0 = Whh[(kb + k8 * 8 + 2 * q)     * H + j];
            float w1 = Whh[(kb + k8 * 8 + 2 * q + 1) * H + j];
            u32 b0 = (u32)__bfloat16_as_ushort(__float2bfloat16(w0));
            u32 b1 = (u32)__bfloat16_as_ushort(__float2bfloat16(w1));
            wrd[q] = (b1 << 16) | b0;
        }
        wreg[k8] = make_uint4(wrd[0], wrd[1], wrd[2], wrd[3]);
    }

    if (kh == 0) {
        hbuf[0][0][j] = 0.f;
        hbuf[0][1][j] = 0.f;
    }
    __syncthreads();

    float* __restrict__ fin = out + (size_t)T * B * 2 * H;

    int t  = dir ? (T - 1) : 0;
    const int dt = dir ? -1 : 1;
    int p = 0;
    float h0 = 0.f, h1 = 0.f;

    // kh=0 threads prefetch x for step 0
    float x0 = 0.f, x1 = 0.f;
    if (kh == 0) {
        const float* xr = xw + ((size_t)t * B + brow) * H + j;
        x0 = __ldg(xr);
        x1 = __ldg(xr + H);
    }

    for (int s = 0; s < T; s++) {
        const float* hr0 = &hbuf[p][0][kb];
        const float* hr1 = &hbuf[p][1][kb];

        u64 acc[2][4];
        #pragma unroll
        for (int r = 0; r < 2; r++)
            #pragma unroll
            for (int q = 0; q < 4; q++) acc[r][q] = 0ull;

        #pragma unroll
        for (int k8 = 0; k8 < NKH; k8++) {
            uint4 w = wreg[k8];
            ulonglong2 a0 = *(const ulonglong2*)&hr0[k8 * 8];
            ulonglong2 a1 = *(const ulonglong2*)&hr0[k8 * 8 + 4];
            ulonglong2 b0 = *(const ulonglong2*)&hr1[k8 * 8];
            ulonglong2 b1 = *(const ulonglong2*)&hr1[k8 * 8 + 4];
            u64 w01 = bfpair(w.x);
            u64 w23 = bfpair(w.y);
            u64 w45 = bfpair(w.z);
            u64 w67 = bfpair(w.w);
            ffma2(acc[0][0], a0.x, w01);
            ffma2(acc[0][1], a0.y, w23);
            ffma2(acc[0][2], a1.x, w45);
            ffma2(acc[0][3], a1.y, w67);
            ffma2(acc[1][0], b0.x, w01);
            ffma2(acc[1][1], b0.y, w23);
            ffma2(acc[1][2], b1.x, w45);
            ffma2(acc[1][3], b1.y, w67);
        }

        // pairwise reduce this thread's partials
        float a0l, a0h, a1l, a1h;
        upk2(a0l, a0h, acc[0][0]); float s0 = a0l + a0h;
        upk2(a0l, a0h, acc[0][1]); s0 += a0l + a0h;
        upk2(a0l, a0h, acc[0][2]); s0 += a0l + a0h;
        upk2(a0l, a0h, acc[0][3]); s0 += a0l + a0h;
        upk2(a1l, a1h, acc[1][0]); float s1 = a1l + a1h;
        upk2(a1l, a1h, acc[1][1]); s1 += a1l + a1h;
        upk2(a1l, a1h, acc[1][2]); s1 += a1l + a1h;
        upk2(a1l, a1h, acc[1][3]); s1 += a1l + a1h;

        float xn0 = 0.f, xn1 = 0.f;
        if (kh) {
            psum[0][j] = s0;
            psum[1][j] = s1;
        } else if (s + 1 < T) {
            // prefetch next x while kh=1 finishes its deposit
            const float* xr2 = xw + ((size_t)(t + dt) * B + brow) * H + j;
            xn0 = __ldg(xr2);
            xn1 = __ldg(xr2 + H);
        }
        __syncthreads();   // barrier1: psum visible

        if (kh == 0) {
            float v0 = x0 + s0 + psum[0][j];
            float v1 = x1 + s1 + psum[1][j];
            h0 = tanh_fast(v0);
            h1 = tanh_fast(v1);
            hbuf[p ^ 1][0][j] = h0;
            hbuf[p ^ 1][1][j] = h1;
            size_t ob = ((size_t)t * B + brow) * (2 * H) + (size_t)dir * H + j;
            out[ob]         = h0;
            out[ob + 2 * H] = h1;
            x0 = xn0;
            x1 = xn1;
        }
        __syncthreads();   // barrier2: new h visible
        p ^= 1;
        t += dt;
    }

    if (kh == 0) {
        size_t fb = (size_t)dir * B * H + (size_t)brow * H + j;
        fin[fb]     = h0;
        fin[fb + H] = h1;
    }
}

// ---------------------------------------------------------------------------
extern "C" void kernel_launch(void* const* d_in, const int* in_sizes, int n_in,
                              void* d_out, int out_size)
{
    const float* inp = (const float*)d_in[0];
    const float* Wxf = (const float*)d_in[1];
    const float* Whf = (const float*)d_in[2];
    const float* bf  = (const float*)d_in[3];
    const float* Wxb = (const float*)d_in[4];
    const float* Whb = (const float*)d_in[5];
    const float* bb  = (const float*)d_in[6];
    float* out = (float*)d_out;

    dim3 g1(T * B / BM, H / BN, 2);
    proj_kernel<<<g1, 256>>>(inp, Wxf, bf, Wxb, bb);

    scan_kernel<<<128, 512>>>(Whf, Whb, out);
}

// round 9
// speedup vs baseline: 1.4021x; 1.4021x over previous
#include <cuda_runtime.h>
#include <cuda_bf16.h>
#include <math.h>

#define T 512
#define B 128
#define D 256
#define H 256

// Scratch for precomputed input projections, one per direction: [T*B, H]
__device__ float g_xw[2][(size_t)T * B * H];

typedef unsigned long long u64;
typedef unsigned int u32;

__device__ __forceinline__ u64 pk2(float lo, float hi) {
    u64 r; asm("mov.b64 %0, {%1, %2};" : "=l"(r) : "f"(lo), "f"(hi)); return r;
}
__device__ __forceinline__ void upk2(float& lo, float& hi, u64 v) {
    asm("mov.b64 {%0, %1}, %2;" : "=f"(lo), "=f"(hi) : "l"(v));
}
__device__ __forceinline__ void ffma2(u64& acc, u64 a, u64 b) {
    asm("fma.rn.f32x2 %0, %1, %2, %3;" : "=l"(acc) : "l"(a), "l"(b), "l"(acc));
}
__device__ __forceinline__ float tanh_fast(float x) {
    float y; asm("tanh.approx.f32 %0, %1;" : "=f"(y) : "f"(x)); return y;
}
// word = (bf16 w_k in low 16, bf16 w_{k+1} in high 16)
// -> u64 fp32 pair (w_k, w_{k+1}); bf16->fp32 expansion is exact.
__device__ __forceinline__ u64 bfpair(u32 w) {
    u64 r;
    asm("{ .reg .b32 lo, hi;\n"
        "  shl.b32 lo, %1, 16;\n"
        "  and.b32 hi, %1, 0xffff0000;\n"
        "  mov.b64 %0, {lo, hi}; }" : "=l"(r) : "r"(w));
    return r;
}

// ---------------------------------------------------------------------------
// Kernel 1: xw[dir] = inputs @ W_xh[dir] + b[dir]   (FFMA2 inner product)
// ---------------------------------------------------------------------------
#define BM 64
#define BN 128
#define BK 16

__global__ __launch_bounds__(256) void proj_kernel(
    const float* __restrict__ inp,
    const float* __restrict__ Wf, const float* __restrict__ bfp,
    const float* __restrict__ Wb, const float* __restrict__ bbp)
{
    const int dir = blockIdx.z;
    const float* __restrict__ Wx   = dir ? Wb : Wf;
    const float* __restrict__ bias = dir ? bbp : bfp;
    float* __restrict__ out = g_xw[dir];

    __shared__ float As[BK][BM + 4];
    __shared__ float Bs[BK][BN];

    const int m0 = blockIdx.x * BM;
    const int n0 = blockIdx.y * BN;

    const int tid = threadIdx.x;
    const int tx  = tid & 31;
    const int ty  = tid >> 5;

    const int am = tid >> 2;
    const int a4 = tid & 3;
    const int bn = tid & 31;
    const int bk = tid >> 5;

    u64 acc2[4][4];
    #pragma unroll
    for (int p = 0; p < 4; p++)
        #pragma unroll
        for (int c = 0; c < 4; c++) acc2[p][c] = 0ull;

    float bv[4];
    #pragma unroll
    for (int c = 0; c < 4; c++) bv[c] = bias[n0 + tx * 4 + c];

    for (int k0 = 0; k0 < D; k0 += BK) {
        {
            float4 v = *(const float4*)&inp[(size_t)(m0 + am) * D + k0 + a4 * 4];
            As[a4 * 4 + 0][am] = v.x;
            As[a4 * 4 + 1][am] = v.y;
            As[a4 * 4 + 2][am] = v.z;
            As[a4 * 4 + 3][am] = v.w;
        }
        {
            float4 v0 = *(const float4*)&Wx[(size_t)(k0 + bk) * H + n0 + bn * 4];
            float4 v1 = *(const float4*)&Wx[(size_t)(k0 + bk + 8) * H + n0 + bn * 4];
            *(float4*)&Bs[bk][bn * 4]     = v0;
            *(float4*)&Bs[bk + 8][bn * 4] = v1;
        }
        __syncthreads();

        #pragma unroll
        for (int kk = 0; kk < BK; kk++) {
            ulonglong2 ap0 = *(const ulonglong2*)&As[kk][ty * 8];
            ulonglong2 ap1 = *(const ulonglong2*)&As[kk][ty * 8 + 4];
            float4 bq = *(const float4*)&Bs[kk][tx * 4];
            u64 bb[4];
            bb[0] = pk2(bq.x, bq.x);
            bb[1] = pk2(bq.y, bq.y);
            bb[2] = pk2(bq.z, bq.z);
            bb[3] = pk2(bq.w, bq.w);
            #pragma unroll
            for (int c = 0; c < 4; c++) {
                ffma2(acc2[0][c], ap0.x, bb[c]);
                ffma2(acc2[1][c], ap0.y, bb[c]);
                ffma2(acc2[2][c], ap1.x, bb[c]);
                ffma2(acc2[3][c], ap1.y, bb[c]);
            }
        }
        __syncthreads();
    }

    #pragma unroll
    for (int p = 0; p < 4; p++) {
        float lo[4], hi[4];
        #pragma unroll
        for (int c = 0; c < 4; c++) upk2(lo[c], hi[c], acc2[p][c]);
        float4 v0 = make_float4(lo[0] + bv[0], lo[1] + bv[1], lo[2] + bv[2], lo[3] + bv[3]);
        float4 v1 = make_float4(hi[0] + bv[0], hi[1] + bv[1], hi[2] + bv[2], hi[3] + bv[3]);
        *(float4*)&out[(size_t)(m0 + ty * 8 + 2 * p)     * H + n0 + tx * 4] = v0;
        *(float4*)&out[(size_t)(m0 + ty * 8 + 2 * p + 1) * H + n0 + tx * 4] = v1;
    }
}

// ---------------------------------------------------------------------------
// Kernel 2: recurrent scan, persistent blocks (128 blocks, 1/SM, 512 thr).
// Split-K: thread (j = tid&255, kh = tid>>8) accumulates k in
// [kh*128, kh*128+128) for output column j. Its 128 bf16 W values live:
//   - 12 uint4 (96 k-values) in REGISTERS
//   -  4 uint4 (32 k-values) in SMEM (conflict-free LDS.128)
// keeping per-thread regs ~110 < the 128 hard cap (the round-8 spill fix).
// kh=1 deposits partials to smem; kh=0 finalizes (x + partials, tanh),
// publishes h (double-buffered), and stores output AFTER the barrier so the
// STG overlaps the next step. 16 warps/SM (4/SMSP) cover rt-2 + LDS latency.
// ---------------------------------------------------------------------------
#define NKH   16   // uint4 words per thread-half (16*8 = 128 k)
#define NREGW 12   // of which in registers
#define NSMW  (NKH - NREGW)

__global__ __launch_bounds__(512, 1) void scan_kernel(
    const float* __restrict__ Whh_f,
    const float* __restrict__ Whh_b,
    float* __restrict__ out)
{
    __shared__ float hbuf[2][2][H];          // [phase][row][col] 4KB
    __shared__ float psum[2][H];             // kh=1 partials     2KB
    __shared__ uint4 Wsm[2 * NSMW * H];      // [(kh*NSMW+q)*H + j] 32KB

    const int blk  = blockIdx.x;      // 0..127
    const int dir  = blk >> 6;
    const int brow = (blk & 63) * 2;
    const float* __restrict__ Whh = dir ? Whh_b : Whh_f;
    const float* __restrict__ xw  = g_xw[dir];

    const int j  = threadIdx.x & 255;   // output column
    const int kh = threadIdx.x >> 8;    // k-half: 0 or 1
    const int kb = kh << 7;             // k base: 0 or 128

    // ---- load this thread's half of W column j (bf16-packed)
    uint4 wreg[NREGW];
    #pragma unroll
    for (int k8 = 0; k8 < NKH; k8++) {
        u32 wrd[4];
        #pragma unroll
        for (int q = 0; q < 4; q++) {
            float w0 = Whh[(kb + k8 * 8 + 2 * q)     * H + j];
            float w1 = Whh[(kb + k8 * 8 + 2 * q + 1) * H + j];
            u32 b0 = (u32)__bfloat16_as_ushort(__float2bfloat16(w0));
            u32 b1 = (u32)__bfloat16_as_ushort(__float2bfloat16(w1));
            wrd[q] = (b1 << 16) | b0;
        }
        uint4 v = make_uint4(wrd[0], wrd[1], wrd[2], wrd[3]);
        if (k8 < NREGW) wreg[k8] = v;
        else            Wsm[(kh * NSMW + (k8 - NREGW)) * H + j] = v;
    }

    if (kh == 0) {
        hbuf[0][0][j] = 0.f;
        hbuf[0][1][j] = 0.f;
    }
    __syncthreads();

    float* __restrict__ fin = out + (size_t)T * B * 2 * H;

    int t  = dir ? (T - 1) : 0;
    const int dt = dir ? -1 : 1;
    int p = 0;
    float h0 = 0.f, h1 = 0.f;

    // kh=0 threads prefetch x for step 0
    float x0 = 0.f, x1 = 0.f;
    if (kh == 0) {
        const float* xr = xw + ((size_t)t * B + brow) * H + j;
        x0 = __ldg(xr);
        x1 = __ldg(xr + H);
    }

    for (int s = 0; s < T; s++) {
        const float* hr0 = &hbuf[p][0][kb];
        const float* hr1 = &hbuf[p][1][kb];

        u64 a00 = 0ull, a01 = 0ull, a10 = 0ull, a11 = 0ull;

        #pragma unroll
        for (int k8 = 0; k8 < NKH; k8++) {
            uint4 w = (k8 < NREGW) ? wreg[k8]
                                   : Wsm[(kh * NSMW + (k8 - NREGW)) * H + j];
            u64 w01 = bfpair(w.x);
            u64 w23 = bfpair(w.y);
            u64 w45 = bfpair(w.z);
            u64 w67 = bfpair(w.w);
            ulonglong2 ar0 = *(const ulonglong2*)&hr0[k8 * 8];
            ulonglong2 ar1 = *(const ulonglong2*)&hr0[k8 * 8 + 4];
            ulonglong2 br0 = *(const ulonglong2*)&hr1[k8 * 8];
            ulonglong2 br1 = *(const ulonglong2*)&hr1[k8 * 8 + 4];
            ffma2(a00, ar0.x, w01);
            ffma2(a01, ar0.y, w23);
            ffma2(a10, br0.x, w01);
            ffma2(a11, br0.y, w23);
            ffma2(a00, ar1.x, w45);
            ffma2(a01, ar1.y, w67);
            ffma2(a10, br1.x, w45);
            ffma2(a11, br1.y, w67);
        }

        float lo, hi;
        upk2(lo, hi, a00); float s0 = lo + hi;
        upk2(lo, hi, a01); s0 += lo + hi;
        upk2(lo, hi, a10); float s1 = lo + hi;
        upk2(lo, hi, a11); s1 += lo + hi;

        float xn0 = 0.f, xn1 = 0.f;
        if (kh) {
            psum[0][j] = s0;
            psum[1][j] = s1;
        } else if (s + 1 < T) {
            // prefetch next x while kh=1 deposits
            const float* xr2 = xw + ((size_t)(t + dt) * B + brow) * H + j;
            xn0 = __ldg(xr2);
            xn1 = __ldg(xr2 + H);
        }
        __syncthreads();   // barrier1: psum visible

        if (kh == 0) {
            float v0 = x0 + s0 + psum[0][j];
            float v1 = x1 + s1 + psum[1][j];
            h0 = tanh_fast(v0);
            h1 = tanh_fast(v1);
            hbuf[p ^ 1][0][j] = h0;
            hbuf[p ^ 1][1][j] = h1;
            x0 = xn0;
            x1 = xn1;
        }
        __syncthreads();   // barrier2: new h visible

        if (kh == 0) {
            // fire-and-forget store, overlaps next step's compute
            size_t ob = ((size_t)t * B + brow) * (2 * H) + (size_t)dir * H + j;
            out[ob]         = h0;
            out[ob + 2 * H] = h1;
        }
        p ^= 1;
        t += dt;
    }

    if (kh == 0) {
        size_t fb = (size_t)dir * B * H + (size_t)brow * H + j;
        fin[fb]     = h0;
        fin[fb + H] = h1;
    }
}

// ---------------------------------------------------------------------------
extern "C" void kernel_launch(void* const* d_in, const int* in_sizes, int n_in,
                              void* d_out, int out_size)
{
    const float* inp = (const float*)d_in[0];
    const float* Wxf = (const float*)d_in[1];
    const float* Whf = (const float*)d_in[2];
    const float* bf  = (const float*)d_in[3];
    const float* Wxb = (const float*)d_in[4];
    const float* Whb = (const float*)d_in[5];
    const float* bb  = (const float*)d_in[6];
    float* out = (float*)d_out;

    dim3 g1(T * B / BM, H / BN, 2);
    proj_kernel<<<g1, 256>>>(inp, Wxf, bf, Wxb, bb);

    scan_kernel<<<128, 512>>>(Whf, Whb, out);
}

// round 10
// speedup vs baseline: 1.6574x; 1.1821x over previous
#include <cuda_runtime.h>
#include <cuda_bf16.h>
#include <math.h>

#define T 512
#define B 128
#define D 256
#define H 256

// Scratch for precomputed input projections, one per direction: [T*B, H]
__device__ float g_xw[2][(size_t)T * B * H];

typedef unsigned long long u64;
typedef unsigned int u32;

__device__ __forceinline__ u64 pk2(float lo, float hi) {
    u64 r; asm("mov.b64 %0, {%1, %2};" : "=l"(r) : "f"(lo), "f"(hi)); return r;
}
__device__ __forceinline__ void upk2(float& lo, float& hi, u64 v) {
    asm("mov.b64 {%0, %1}, %2;" : "=f"(lo), "=f"(hi) : "l"(v));
}
__device__ __forceinline__ void ffma2(u64& acc, u64 a, u64 b) {
    asm("fma.rn.f32x2 %0, %1, %2, %3;" : "=l"(acc) : "l"(a), "l"(b), "l"(acc));
}
__device__ __forceinline__ float tanh_fast(float x) {
    float y; asm("tanh.approx.f32 %0, %1;" : "=f"(y) : "f"(x)); return y;
}
// word = (bf16 w_k lo16, bf16 w_{k+1} hi16) -> fp32 pair (exact expansion)
__device__ __forceinline__ u64 bfpair(u32 w) {
    u64 r;
    asm("{ .reg .b32 lo, hi;\n"
        "  shl.b32 lo, %1, 16;\n"
        "  and.b32 hi, %1, 0xffff0000;\n"
        "  mov.b64 %0, {lo, hi}; }" : "=l"(r) : "r"(w));
    return r;
}
__device__ __forceinline__ void cp_async16(void* smem_dst, const void* gptr) {
    u32 saddr = (u32)__cvta_generic_to_shared(smem_dst);
    asm volatile("cp.async.ca.shared.global [%0], [%1], 16;\n"
                 :: "r"(saddr), "l"(gptr));
}
__device__ __forceinline__ void cp_commit() {
    asm volatile("cp.async.commit_group;\n");
}

// ---------------------------------------------------------------------------
// Kernel 1: xw[dir] = inputs @ W_xh[dir] + b[dir]
// BM=128 x BN=128 tile, BK=16, 256 threads, 8x8 micro-tile, FFMA2 math,
// cp.async 2-stage double buffering (FMA-bound: issue ~768 < FMA 2048/tile).
// ---------------------------------------------------------------------------
#define BM 128
#define BN 128
#define BK 16
#define APAD 4     // As row stride 20 floats = 80B (16B-aligned)

__global__ __launch_bounds__(256) void proj_kernel(
    const float* __restrict__ inp,
    const float* __restrict__ Wf, const float* __restrict__ bfp,
    const float* __restrict__ Wb, const float* __restrict__ bbp)
{
    const int dir = blockIdx.z;
    const float* __restrict__ Wx   = dir ? Wb : Wf;
    const float* __restrict__ bias = dir ? bbp : bfp;
    float* __restrict__ out = g_xw[dir];

    __shared__ float As[2][BM][BK + APAD];   // [stage][m][k]
    __shared__ float Bs[2][BK][BN];          // [stage][k][n]

    const int m0 = blockIdx.x * BM;
    const int n0 = blockIdx.y * BN;

    const int tid = threadIdx.x;
    const int tr  = tid >> 4;      // 0..15 : rows m0 + tr*8 .. +7
    const int tc  = tid & 15;      // 0..15 : cols n0 + tc*8 .. +7

    // A copy mapping: 512 16B-chunks; thread handles chunks tid, tid+256
    // chunk c -> (m = c>>2, k4 = c&3)
    // B copy mapping: chunk c -> (k = c>>5, n4 = c&31)
    const int am0 = tid >> 2, ak0 = tid & 3;
    const int am1 = (tid + 256) >> 2, ak1 = (tid + 256) & 3;
    const int bk0 = tid >> 5, bn0 = tid & 31;
    const int bk1 = (tid + 256) >> 5, bn1 = (tid + 256) & 31;

    u64 acc[4][8];
    #pragma unroll
    for (int rp = 0; rp < 4; rp++)
        #pragma unroll
        for (int c = 0; c < 8; c++) acc[rp][c] = 0ull;

    float bv[8];
    #pragma unroll
    for (int c = 0; c < 8; c++) bv[c] = bias[n0 + tc * 8 + c];

    // prefetch stage 0
    {
        const int k0 = 0;
        cp_async16(&As[0][am0][ak0 * 4], &inp[(size_t)(m0 + am0) * D + k0 + ak0 * 4]);
        cp_async16(&As[0][am1][ak1 * 4], &inp[(size_t)(m0 + am1) * D + k0 + ak1 * 4]);
        cp_async16(&Bs[0][bk0][bn0 * 4], &Wx[(size_t)(k0 + bk0) * H + n0 + bn0 * 4]);
        cp_async16(&Bs[0][bk1][bn1 * 4], &Wx[(size_t)(k0 + bk1) * H + n0 + bn1 * 4]);
        cp_commit();
    }

    const int NT = D / BK;   // 16
    for (int i = 0; i < NT; i++) {
        if (i + 1 < NT) {
            const int k0 = (i + 1) * BK;
            const int st = (i + 1) & 1;
            cp_async16(&As[st][am0][ak0 * 4], &inp[(size_t)(m0 + am0) * D + k0 + ak0 * 4]);
            cp_async16(&As[st][am1][ak1 * 4], &inp[(size_t)(m0 + am1) * D + k0 + ak1 * 4]);
            cp_async16(&Bs[st][bk0][bn0 * 4], &Wx[(size_t)(k0 + bk0) * H + n0 + bn0 * 4]);
            cp_async16(&Bs[st][bk1][bn1 * 4], &Wx[(size_t)(k0 + bk1) * H + n0 + bn1 * 4]);
            cp_commit();
            asm volatile("cp.async.wait_group 1;\n");
        } else {
            asm volatile("cp.async.wait_group 0;\n");
        }
        __syncthreads();

        const int st = i & 1;
        #pragma unroll
        for (int k4 = 0; k4 < 4; k4++) {
            float4 av[8];
            #pragma unroll
            for (int r = 0; r < 8; r++)
                av[r] = *(const float4*)&As[st][tr * 8 + r][k4 * 4];

            #pragma unroll
            for (int q = 0; q < 4; q++) {
                float4 b0 = *(const float4*)&Bs[st][k4 * 4 + q][tc * 8];
                float4 b1 = *(const float4*)&Bs[st][k4 * 4 + q][tc * 8 + 4];
                u64 bb[8];
                bb[0] = pk2(b0.x, b0.x); bb[1] = pk2(b0.y, b0.y);
                bb[2] = pk2(b0.z, b0.z); bb[3] = pk2(b0.w, b0.w);
                bb[4] = pk2(b1.x, b1.x); bb[5] = pk2(b1.y, b1.y);
                bb[6] = pk2(b1.z, b1.z); bb[7] = pk2(b1.w, b1.w);
                #pragma unroll
                for (int rp = 0; rp < 4; rp++) {
                    u64 a = pk2(((const float*)&av[2 * rp])[q],
                                ((const float*)&av[2 * rp + 1])[q]);
                    #pragma unroll
                    for (int c = 0; c < 8; c++) ffma2(acc[rp][c], a, bb[c]);
                }
            }
        }
        __syncthreads();   // protect buffers before next issue into this stage
    }

    // epilogue
    #pragma unroll
    for (int rp = 0; rp < 4; rp++) {
        float lo[8], hi[8];
        #pragma unroll
        for (int c = 0; c < 8; c++) upk2(lo[c], hi[c], acc[rp][c]);
        float4 e0 = make_float4(lo[0] + bv[0], lo[1] + bv[1], lo[2] + bv[2], lo[3] + bv[3]);
        float4 e1 = make_float4(lo[4] + bv[4], lo[5] + bv[5], lo[6] + bv[6], lo[7] + bv[7]);
        float4 o0 = make_float4(hi[0] + bv[0], hi[1] + bv[1], hi[2] + bv[2], hi[3] + bv[3]);
        float4 o1 = make_float4(hi[4] + bv[4], hi[5] + bv[5], hi[6] + bv[6], hi[7] + bv[7]);
        size_t row_e = (size_t)(m0 + tr * 8 + 2 * rp) * H + n0 + tc * 8;
        size_t row_o = row_e + H;
        *(float4*)&out[row_e]     = e0;
        *(float4*)&out[row_e + 4] = e1;
        *(float4*)&out[row_o]     = o0;
        *(float4*)&out[row_o + 4] = o1;
    }
}

// ---------------------------------------------------------------------------
// Kernel 2: recurrent scan — round-7 structure with register slack restored.
// 128 blocks (1/SM), 256 threads; thread j owns column j, r=2 batch rows.
// W column j (bf16-packed): 26 uint4 in REGISTERS + 6 uint4 in SMEM (24KB),
// leaving ~80 free regs so ptxas can pipeline the h-broadcast LDS loads.
// One barrier per step (double-buffered h). fp32 math via fma.rn.f32x2.
// ---------------------------------------------------------------------------
#define NK8  32   // uint4 per column (32*8 = 256 k)
#define NREG 26
#define NSM  (NK8 - NREG)

__global__ __launch_bounds__(256, 1) void scan_kernel(
    const float* __restrict__ Whh_f,
    const float* __restrict__ Whh_b,
    float* __restrict__ out)
{
    __shared__ float hbuf[2][2][H];   // [phase][row][col] 4KB
    __shared__ uint4 Wsm[NSM * H];    // 24KB

    const int blk  = blockIdx.x;      // 0..127
    const int dir  = blk >> 6;
    const int brow = (blk & 63) * 2;
    const float* __restrict__ Whh = dir ? Whh_b : Whh_f;
    const float* __restrict__ xw  = g_xw[dir];
    const int j = threadIdx.x;        // 0..255 (output column)

    // ---- load W column j (bf16-packed, lo=w_k hi=w_{k+1})
    uint4 wreg[NREG];
    #pragma unroll
    for (int k8 = 0; k8 < NK8; k8++) {
        u32 wrd[4];
        #pragma unroll
        for (int q = 0; q < 4; q++) {
            float w0 = Whh[(k8 * 8 + 2 * q)     * H + j];
            float w1 = Whh[(k8 * 8 + 2 * q + 1) * H + j];
            u32 b0 = (u32)__bfloat16_as_ushort(__float2bfloat16(w0));
            u32 b1 = (u32)__bfloat16_as_ushort(__float2bfloat16(w1));
            wrd[q] = (b1 << 16) | b0;
        }
        uint4 v = make_uint4(wrd[0], wrd[1], wrd[2], wrd[3]);
        if (k8 < NREG) wreg[k8] = v;
        else           Wsm[(k8 - NREG) * H + j] = v;
    }

    hbuf[0][0][j] = 0.f;
    hbuf[0][1][j] = 0.f;
    __syncthreads();

    float* __restrict__ fin = out + (size_t)T * B * 2 * H;

    int t  = dir ? (T - 1) : 0;
    const int dt = dir ? -1 : 1;
    int p = 0;
    float h0 = 0.f, h1 = 0.f;

    // prefetch x for step 0
    const float* xr = xw + ((size_t)t * B + brow) * H + j;
    float x0 = __ldg(xr);
    float x1 = __ldg(xr + H);

    for (int s = 0; s < T; s++) {
        // prefetch x for next step
        float xn0 = 0.f, xn1 = 0.f;
        if (s + 1 < T) {
            const float* xr2 = xw + ((size_t)(t + dt) * B + brow) * H + j;
            xn0 = __ldg(xr2);
            xn1 = __ldg(xr2 + H);
        }

        const float* hr0 = &hbuf[p][0][0];
        const float* hr1 = &hbuf[p][1][0];

        u64 acc[2][4];
        #pragma unroll
        for (int r = 0; r < 2; r++)
            #pragma unroll
            for (int q = 0; q < 4; q++) acc[r][q] = 0ull;

        #pragma unroll
        for (int k8 = 0; k8 < NK8; k8++) {
            uint4 w = (k8 < NREG) ? wreg[k8] : Wsm[(k8 - NREG) * H + j];
            ulonglong2 a0 = *(const ulonglong2*)&hr0[k8 * 8];
            ulonglong2 a1 = *(const ulonglong2*)&hr0[k8 * 8 + 4];
            ulonglong2 b0 = *(const ulonglong2*)&hr1[k8 * 8];
            ulonglong2 b1 = *(const ulonglong2*)&hr1[k8 * 8 + 4];
            u64 w01 = bfpair(w.x);
            u64 w23 = bfpair(w.y);
            u64 w45 = bfpair(w.z);
            u64 w67 = bfpair(w.w);
            ffma2(acc[0][0], a0.x, w01);
            ffma2(acc[0][1], a0.y, w23);
            ffma2(acc[0][2], a1.x, w45);
            ffma2(acc[0][3], a1.y, w67);
            ffma2(acc[1][0], b0.x, w01);
            ffma2(acc[1][1], b0.y, w23);
            ffma2(acc[1][2], b1.x, w45);
            ffma2(acc[1][3], b1.y, w67);
        }

        float lo, hi;
        upk2(lo, hi, acc[0][0]); float s0 = x0 + lo + hi;
        upk2(lo, hi, acc[0][1]); s0 += lo + hi;
        upk2(lo, hi, acc[0][2]); s0 += lo + hi;
        upk2(lo, hi, acc[0][3]); s0 += lo + hi;
        upk2(lo, hi, acc[1][0]); float s1 = x1 + lo + hi;
        upk2(lo, hi, acc[1][1]); s1 += lo + hi;
        upk2(lo, hi, acc[1][2]); s1 += lo + hi;
        upk2(lo, hi, acc[1][3]); s1 += lo + hi;

        h0 = tanh_fast(s0);
        h1 = tanh_fast(s1);

        // publish new h into the other buffer
        hbuf[p ^ 1][0][j] = h0;
        hbuf[p ^ 1][1][j] = h1;

        // output store (fire-and-forget)
        size_t ob = ((size_t)t * B + brow) * (2 * H) + (size_t)dir * H + j;
        out[ob]         = h0;
        out[ob + 2 * H] = h1;

        __syncthreads();
        p ^= 1;
        t += dt;
        x0 = xn0;
        x1 = xn1;
    }

    size_t fb = (size_t)dir * B * H + (size_t)brow * H + j;
    fin[fb]     = h0;
    fin[fb + H] = h1;
}

// ---------------------------------------------------------------------------
extern "C" void kernel_launch(void* const* d_in, const int* in_sizes, int n_in,
                              void* d_out, int out_size)
{
    const float* inp = (const float*)d_in[0];
    const float* Wxf = (const float*)d_in[1];
    const float* Whf = (const float*)d_in[2];
    const float* bf  = (const float*)d_in[3];
    const float* Wxb = (const float*)d_in[4];
    const float* Whb = (const float*)d_in[5];
    const float* bb  = (const float*)d_in[6];
    float* out = (float*)d_out;

    dim3 g1(T * B / BM, H / BN, 2);
    proj_kernel<<<g1, 256>>>(inp, Wxf, bf, Wxb, bb);

    scan_kernel<<<128, 256>>>(Whf, Whb, out);
}

// round 12
// speedup vs baseline: 1.6832x; 1.0156x over previous
#include <cuda_runtime.h>
#include <cuda_bf16.h>
#include <math.h>

#define T 512
#define B 128
#define D 256
#define H 256

// Scratch for precomputed input projections, one per direction: [T*B, H]
__device__ float g_xw[2][(size_t)T * B * H];

typedef unsigned long long u64;
typedef unsigned int u32;

__device__ __forceinline__ u64 pk2(float lo, float hi) {
    u64 r; asm("mov.b64 %0, {%1, %2};" : "=l"(r) : "f"(lo), "f"(hi)); return r;
}
__device__ __forceinline__ void upk2(float& lo, float& hi, u64 v) {
    asm("mov.b64 {%0, %1}, %2;" : "=f"(lo), "=f"(hi) : "l"(v));
}
__device__ __forceinline__ void ffma2(u64& acc, u64 a, u64 b) {
    asm("fma.rn.f32x2 %0, %1, %2, %3;" : "=l"(acc) : "l"(a), "l"(b), "l"(acc));
}
__device__ __forceinline__ float tanh_fast(float x) {
    float y; asm("tanh.approx.f32 %0, %1;" : "=f"(y) : "f"(x)); return y;
}
// u32 = (bf16 e_k lo16, bf16 e_{k+1} hi16) -> fp32 pair (exact expansion)
__device__ __forceinline__ u64 bfpair(u32 w) {
    u64 r;
    asm("{ .reg .b32 lo, hi;\n"
        "  shl.b32 lo, %1, 16;\n"
        "  and.b32 hi, %1, 0xffff0000;\n"
        "  mov.b64 %0, {lo, hi}; }" : "=l"(r) : "r"(w));
    return r;
}
// pack two f32 into bf16x2: lo16 = cvt(vlo), hi16 = cvt(vhi)
__device__ __forceinline__ u32 cvt_bf16x2(float vhi, float vlo) {
    u32 d; asm("cvt.rn.bf16x2.f32 %0, %1, %2;" : "=r"(d) : "f"(vhi), "f"(vlo));
    return d;
}

// mma.sync m16n8k16 row.col bf16 -> f32 accum (sm_80+, no arch-a needed)
__device__ __forceinline__ void mma_bf16(float* c, u32 a0, u32 a1, u32 a2, u32 a3,
                                         u32 b0, u32 b1) {
    asm volatile(
        "mma.sync.aligned.m16n8k16.row.col.f32.bf16.bf16.f32 "
        "{%0,%1,%2,%3}, {%4,%5,%6,%7}, {%8,%9}, {%0,%1,%2,%3};"
        : "+f"(c[0]), "+f"(c[1]), "+f"(c[2]), "+f"(c[3])
        : "r"(a0), "r"(a1), "r"(a2), "r"(a3), "r"(b0), "r"(b1));
}

// ---------------------------------------------------------------------------
// Kernel 1: xw[dir] = inputs @ W_xh[dir] + b[dir] via HMMA bf16 3-term split.
// Grid (TB/128, H/128, 2 dirs), 256 threads (8 warps, 4M x 2N).
// Smem tiles (128B rows, 16B-chunk XOR swizzle c^=(row&7)):
//   Ah/Al: [128 m][64 k] bf16   Bh/Bl: [128 n][64 k] bf16 (B = W^T)
// K processed in 4 chunks of 64; per chunk 4 k16 MMA steps x 3 split terms.
// ---------------------------------------------------------------------------
#define SM_AH 0
#define SM_AL (128 * 128)
#define SM_BH (2 * 128 * 128)
#define SM_BL (3 * 128 * 128)
#define PROJ_SMEM (4 * 128 * 128)     // 64KB

__device__ __forceinline__ u32 sw_off(int row, int k) {
    // byte offset of element (row, k) in a [128 rows x 64 bf16] swizzled tile
    return (u32)(row * 128 + (((k >> 3) ^ (row & 7)) << 4) + (k & 7) * 2);
}

__global__ __launch_bounds__(256) void proj_tc_kernel(
    const float* __restrict__ inp,
    const float* __restrict__ Wf, const float* __restrict__ bfp,
    const float* __restrict__ Wb, const float* __restrict__ bbp)
{
    extern __shared__ char smem[];

    const int dir = blockIdx.z;
    const float* __restrict__ Wx   = dir ? Wb : Wf;
    const float* __restrict__ bias = dir ? bbp : bfp;
    float* __restrict__ out = g_xw[dir];

    const int m0  = blockIdx.x * 128;
    const int n0t = blockIdx.y * 128;

    const int tid  = threadIdx.x;
    const int lane = tid & 31;
    const int wid  = tid >> 5;
    const int gid  = lane >> 2;     // 0..7
    const int tig  = lane & 3;      // 0..3
    const int wm   = wid & 3;       // M-warp: rows 32*wm..+31
    const int wn   = wid >> 2;      // N-warp: cols 64*wn..+63
    const int rbase = 32 * wm;
    const int nbase = 64 * wn;

    float acc[2][8][4];
    #pragma unroll
    for (int mf = 0; mf < 2; mf++)
        #pragma unroll
        for (int nf = 0; nf < 8; nf++)
            #pragma unroll
            for (int q = 0; q < 4; q++) acc[mf][nf][q] = 0.f;

    for (int c = 0; c < 4; c++) {
        const int kc0 = c * 64;
        __syncthreads();   // previous chunk math done before overwrite

        // ---- stage A: 128 m x 64 k, float4 per thread x 8
        for (int i = tid; i < 2048; i += 256) {
            int m = i >> 4, k4 = i & 15, k = 4 * k4;
            float4 v = *(const float4*)&inp[(size_t)(m0 + m) * D + kc0 + k];
            u32 h01 = cvt_bf16x2(v.y, v.x);
            u32 h23 = cvt_bf16x2(v.w, v.z);
            float e0 = __uint_as_float(h01 << 16);
            float e1 = __uint_as_float(h01 & 0xffff0000u);
            float e2 = __uint_as_float(h23 << 16);
            float e3 = __uint_as_float(h23 & 0xffff0000u);
            u32 l01 = cvt_bf16x2(v.y - e1, v.x - e0);
            u32 l23 = cvt_bf16x2(v.w - e3, v.z - e2);
            u32 off = sw_off(m, k);
            *(uint2*)(smem + SM_AH + off) = make_uint2(h01, h23);
            *(uint2*)(smem + SM_AL + off) = make_uint2(l01, l23);
        }
        // ---- stage B = W^T: 128 n x 64 k (transpose W[k][n] during store)
        for (int i = tid; i < 2048; i += 256) {
            int kk = i >> 5, n4 = i & 31, n = 4 * n4;
            float4 w = *(const float4*)&Wx[(size_t)(kc0 + kk) * H + n0t + n];
            float wv[4] = {w.x, w.y, w.z, w.w};
            #pragma unroll
            for (int e = 0; e < 4; e++) {
                __nv_bfloat16 hb = __float2bfloat16(wv[e]);
                float eh = __bfloat162float(hb);
                __nv_bfloat16 lb = __float2bfloat16(wv[e] - eh);
                u32 off = sw_off(n + e, kk);
                *(__nv_bfloat16*)(smem + SM_BH + off) = hb;
                *(__nv_bfloat16*)(smem + SM_BL + off) = lb;
            }
        }
        __syncthreads();

        // ---- math: 4 k16 steps
        #pragma unroll
        for (int ks = 0; ks < 4; ks++) {
            const int k0 = 16 * ks;           // chunk-local k base
            u32 ah[2][4], al[2][4];
            #pragma unroll
            for (int mf = 0; mf < 2; mf++) {
                int r0 = rbase + 16 * mf + gid;
                int r1 = r0 + 8;
                u32 o00 = sw_off(r0, k0 + 2 * tig);
                u32 o10 = sw_off(r1, k0 + 2 * tig);
                u32 o01 = sw_off(r0, k0 + 8 + 2 * tig);
                u32 o11 = sw_off(r1, k0 + 8 + 2 * tig);
                ah[mf][0] = *(const u32*)(smem + SM_AH + o00);
                ah[mf][1] = *(const u32*)(smem + SM_AH + o10);
                ah[mf][2] = *(const u32*)(smem + SM_AH + o01);
                ah[mf][3] = *(const u32*)(smem + SM_AH + o11);
                al[mf][0] = *(const u32*)(smem + SM_AL + o00);
                al[mf][1] = *(const u32*)(smem + SM_AL + o10);
                al[mf][2] = *(const u32*)(smem + SM_AL + o01);
                al[mf][3] = *(const u32*)(smem + SM_AL + o11);
            }
            #pragma unroll
            for (int nf = 0; nf < 8; nf++) {
                int n = nbase + 8 * nf + gid;
                u32 ob0 = sw_off(n, k0 + 2 * tig);
                u32 ob1 = sw_off(n, k0 + 8 + 2 * tig);
                u32 bh0 = *(const u32*)(smem + SM_BH + ob0);
                u32 bh1 = *(const u32*)(smem + SM_BH + ob1);
                u32 bl0 = *(const u32*)(smem + SM_BL + ob0);
                u32 bl1 = *(const u32*)(smem + SM_BL + ob1);
                #pragma unroll
                for (int mf = 0; mf < 2; mf++) {
                    mma_bf16(acc[mf][nf], ah[mf][0], ah[mf][1], ah[mf][2], ah[mf][3], bh0, bh1);
                    mma_bf16(acc[mf][nf], ah[mf][0], ah[mf][1], ah[mf][2], ah[mf][3], bl0, bl1);
                    mma_bf16(acc[mf][nf], al[mf][0], al[mf][1], al[mf][2], al[mf][3], bh0, bh1);
                }
            }
        }
    }

    // ---- epilogue: bias + store (c0,c1)=(gid,2tig..+1), (c2,c3)=(gid+8,...)
    #pragma unroll
    for (int nf = 0; nf < 8; nf++) {
        int ncol = n0t + nbase + 8 * nf + 2 * tig;
        float2 bv = *(const float2*)&bias[ncol];
        #pragma unroll
        for (int mf = 0; mf < 2; mf++) {
            int row0 = m0 + rbase + 16 * mf + gid;
            int row1 = row0 + 8;
            *(float2*)&out[(size_t)row0 * H + ncol] =
                make_float2(acc[mf][nf][0] + bv.x, acc[mf][nf][1] + bv.y);
            *(float2*)&out[(size_t)row1 * H + ncol] =
                make_float2(acc[mf][nf][2] + bv.x, acc[mf][nf][3] + bv.y);
        }
    }
}

// ---------------------------------------------------------------------------
// Kernel 2: recurrent scan (round-7 version, proven 675us).
// 128 blocks (1/SM), 256 threads; thread j owns column j, 2 batch rows;
// full bf16 W column in 32 uint4 registers; h double-buffered in smem;
// one barrier per step; fp32 math via fma.rn.f32x2.
// ---------------------------------------------------------------------------
#define NK8 (H / 8)                 // 32

__global__ __launch_bounds__(256, 1) void scan_kernel(
    const float* __restrict__ Whh_f,
    const float* __restrict__ Whh_b,
    float* __restrict__ out)
{
    __shared__ float hbuf[2 * 2 * H];

    const int blk  = blockIdx.x;      // 0..127
    const int dir  = blk >> 6;
    const int brow = (blk & 63) * 2;
    const float* __restrict__ Whh = dir ? Whh_b : Whh_f;
    const float* __restrict__ xw  = g_xw[dir];
    const int j = threadIdx.x;        // 0..255 (output column)

    uint4 wreg[NK8];
    #pragma unroll
    for (int k8 = 0; k8 < NK8; k8++) {
        u32 wrd[4];
        #pragma unroll
        for (int q = 0; q < 4; q++) {
            float w0 = Whh[(k8 * 8 + 2 * q)     * H + j];
            float w1 = Whh[(k8 * 8 + 2 * q + 1) * H + j];
            u32 b0 = (u32)__bfloat16_as_ushort(__float2bfloat16(w0));
            u32 b1 = (u32)__bfloat16_as_ushort(__float2bfloat16(w1));
            wrd[q] = (b1 << 16) | b0;
        }
        wreg[k8] = make_uint4(wrd[0], wrd[1], wrd[2], wrd[3]);
    }

    hbuf[j] = 0.f;
    hbuf[H + j] = 0.f;
    __syncthreads();

    float* __restrict__ fin = out + (size_t)T * B * 2 * H;

    int t  = dir ? (T - 1) : 0;
    const int dt = dir ? -1 : 1;
    int p = 0;
    float h0 = 0.f, h1 = 0.f;

    const float* xr = xw + ((size_t)t * B + brow) * H + j;
    float x0 = __ldg(xr);
    float x1 = __ldg(xr + H);

    for (int s = 0; s < T; s++) {
        float xn0 = 0.f, xn1 = 0.f;
        if (s + 1 < T) {
            const float* xr2 = xw + ((size_t)(t + dt) * B + brow) * H + j;
            xn0 = __ldg(xr2);
            xn1 = __ldg(xr2 + H);
        }

        const float* hr0 = hbuf + p * (2 * H);
        const float* hr1 = hr0 + H;

        u64 acc[2][4];
        #pragma unroll
        for (int r = 0; r < 2; r++)
            #pragma unroll
            for (int q = 0; q < 4; q++) acc[r][q] = 0ull;

        #pragma unroll
        for (int k8 = 0; k8 < NK8; k8++) {
            uint4 w = wreg[k8];
            ulonglong2 a0 = *(const ulonglong2*)&hr0[k8 * 8];
            ulonglong2 a1 = *(const ulonglong2*)&hr0[k8 * 8 + 4];
            ulonglong2 b0 = *(const ulonglong2*)&hr1[k8 * 8];
            ulonglong2 b1 = *(const ulonglong2*)&hr1[k8 * 8 + 4];
            u64 w01 = bfpair(w.x);
            u64 w23 = bfpair(w.y);
            u64 w45 = bfpair(w.z);
            u64 w67 = bfpair(w.w);
            ffma2(acc[0][0], a0.x, w01);
            ffma2(acc[0][1], a0.y, w23);
            ffma2(acc[0][2], a1.x, w45);
            ffma2(acc[0][3], a1.y, w67);
            ffma2(acc[1][0], b0.x, w01);
            ffma2(acc[1][1], b0.y, w23);
            ffma2(acc[1][2], b1.x, w45);
            ffma2(acc[1][3], b1.y, w67);
        }

        float lo, hi;
        upk2(lo, hi, acc[0][0]); float s0 = x0 + lo + hi;
        upk2(lo, hi, acc[0][1]); s0 += lo + hi;
        upk2(lo, hi, acc[0][2]); s0 += lo + hi;
        upk2(lo, hi, acc[0][3]); s0 += lo + hi;
        upk2(lo, hi, acc[1][0]); float s1 = x1 + lo + hi;
        upk2(lo, hi, acc[1][1]); s1 += lo + hi;
        upk2(lo, hi, acc[1][2]); s1 += lo + hi;
        upk2(lo, hi, acc[1][3]); s1 += lo + hi;

        h0 = tanh_fast(s0);
        h1 = tanh_fast(s1);

        hbuf[(p ^ 1) * (2 * H) + j]     = h0;
        hbuf[(p ^ 1) * (2 * H) + H + j] = h1;

        size_t ob = ((size_t)t * B + brow) * (2 * H) + (size_t)dir * H + j;
        out[ob]         = h0;
        out[ob + 2 * H] = h1;

        __syncthreads();
        p ^= 1;
        t += dt;
        x0 = xn0;
        x1 = xn1;
    }

    size_t fb = (size_t)dir * B * H + (size_t)brow * H + j;
    fin[fb]     = h0;
    fin[fb + H] = h1;
}

// ---------------------------------------------------------------------------
extern "C" void kernel_launch(void* const* d_in, const int* in_sizes, int n_in,
                              void* d_out, int out_size)
{
    const float* inp = (const float*)d_in[0];
    const float* Wxf = (const float*)d_in[1];
    const float* Whf = (const float*)d_in[2];
    const float* bf  = (const float*)d_in[3];
    const float* Wxb = (const float*)d_in[4];
    const float* Whb = (const float*)d_in[5];
    const float* bb  = (const float*)d_in[6];
    float* out = (float*)d_out;

    cudaFuncSetAttribute(proj_tc_kernel,
                         cudaFuncAttributeMaxDynamicSharedMemorySize, PROJ_SMEM);
    dim3 g1(T * B / 128, H / 128, 2);
    proj_tc_kernel<<<g1, 256, PROJ_SMEM>>>(inp, Wxf, bf, Wxb, bb);

    scan_kernel<<<128, 256>>>(Whf, Whb, out);
}

// round 13
// speedup vs baseline: 2.0035x; 1.1903x over previous
#include <cuda_runtime.h>
#include <cuda_bf16.h>
#include <math.h>

#define T 512
#define B 128
#define D 256
#define H 256
#define TBD (T * B * D)

// Scratch: input projections per direction, bf16 split arrays for proj GEMM.
__device__ float g_xw[2][(size_t)T * B * H];
__device__ uint4 g_xh4[TBD / 8];            // x hi bf16, [m][k] k-major, 8/uint4
__device__ uint4 g_xl4[TBD / 8];            // x lo residual bf16
__device__ uint4 g_wth4[2][H * D / 8];      // W^T hi bf16, [n][k] k-major
__device__ uint4 g_wtl4[2][H * D / 8];      // W^T lo residual

typedef unsigned long long u64;
typedef unsigned int u32;

__device__ __forceinline__ u64 pk2(float lo, float hi) {
    u64 r; asm("mov.b64 %0, {%1, %2};" : "=l"(r) : "f"(lo), "f"(hi)); return r;
}
__device__ __forceinline__ void upk2(float& lo, float& hi, u64 v) {
    asm("mov.b64 {%0, %1}, %2;" : "=f"(lo), "=f"(hi) : "l"(v));
}
__device__ __forceinline__ void ffma2(u64& acc, u64 a, u64 b) {
    asm("fma.rn.f32x2 %0, %1, %2, %3;" : "=l"(acc) : "l"(a), "l"(b), "l"(acc));
}
__device__ __forceinline__ float tanh_fast(float x) {
    float y; asm("tanh.approx.f32 %0, %1;" : "=f"(y) : "f"(x)); return y;
}
__device__ __forceinline__ u64 bfpair(u32 w) {
    u64 r;
    asm("{ .reg .b32 lo, hi;\n"
        "  shl.b32 lo, %1, 16;\n"
        "  and.b32 hi, %1, 0xffff0000;\n"
        "  mov.b64 %0, {lo, hi}; }" : "=l"(r) : "r"(w));
    return r;
}
// pack two f32 into bf16x2: lo16 = cvt(vlo), hi16 = cvt(vhi)
__device__ __forceinline__ u32 cvt_bf16x2(float vhi, float vlo) {
    u32 d; asm("cvt.rn.bf16x2.f32 %0, %1, %2;" : "=r"(d) : "f"(vhi), "f"(vlo));
    return d;
}
__device__ __forceinline__ void cp_async16(void* smem_dst, const void* gptr) {
    u32 saddr = (u32)__cvta_generic_to_shared(smem_dst);
    asm volatile("cp.async.cg.shared.global [%0], [%1], 16;\n" :: "r"(saddr), "l"(gptr));
}

// mma.sync m16n8k16 row.col bf16 -> f32 accum
__device__ __forceinline__ void mma_bf16(float* c, u32 a0, u32 a1, u32 a2, u32 a3,
                                         u32 b0, u32 b1) {
    asm volatile(
        "mma.sync.aligned.m16n8k16.row.col.f32.bf16.bf16.f32 "
        "{%0,%1,%2,%3}, {%4,%5,%6,%7}, {%8,%9}, {%0,%1,%2,%3};"
        : "+f"(c[0]), "+f"(c[1]), "+f"(c[2]), "+f"(c[3])
        : "r"(a0), "r"(a1), "r"(a2), "r"(a3), "r"(b0), "r"(b1));
}

// ---------------------------------------------------------------------------
// Convert kernels (run once, before proj)
// ---------------------------------------------------------------------------
__global__ __launch_bounds__(256) void cvt_x_kernel(const float* __restrict__ inp)
{
    size_t i = (size_t)blockIdx.x * 256 + threadIdx.x;   // over TBD/8
    const float4* p = (const float4*)inp + i * 2;
    float4 v0 = p[0], v1 = p[1];
    u32 h0 = cvt_bf16x2(v0.y, v0.x);
    u32 h1 = cvt_bf16x2(v0.w, v0.z);
    u32 h2 = cvt_bf16x2(v1.y, v1.x);
    u32 h3 = cvt_bf16x2(v1.w, v1.z);
    float e;
    u32 l0, l1, l2, l3;
    {
        float a0 = __uint_as_float(h0 << 16), a1 = __uint_as_float(h0 & 0xffff0000u);
        l0 = cvt_bf16x2(v0.y - a1, v0.x - a0);
        float b0 = __uint_as_float(h1 << 16), b1 = __uint_as_float(h1 & 0xffff0000u);
        l1 = cvt_bf16x2(v0.w - b1, v0.z - b0);
        float c0 = __uint_as_float(h2 << 16), c1 = __uint_as_float(h2 & 0xffff0000u);
        l2 = cvt_bf16x2(v1.y - c1, v1.x - c0);
        float d0 = __uint_as_float(h3 << 16), d1 = __uint_as_float(h3 & 0xffff0000u);
        l3 = cvt_bf16x2(v1.w - d1, v1.z - d0);
    }
    (void)e;
    g_xh4[i] = make_uint4(h0, h1, h2, h3);
    g_xl4[i] = make_uint4(l0, l1, l2, l3);
}

__global__ __launch_bounds__(256) void cvt_w_kernel(const float* __restrict__ Wf,
                                                    const float* __restrict__ Wb)
{
    int i = blockIdx.x * 256 + threadIdx.x;     // over 2 * H * (D/8)
    const int per = H * (D / 8);
    int dir = i / per;
    int idx = i - dir * per;
    int n  = idx >> 5;          // D/8 = 32
    int kc = idx & 31;
    int k0 = kc * 8;
    const float* W = dir ? Wb : Wf;
    u32 hh[4], ll[4];
    #pragma unroll
    for (int q = 0; q < 4; q++) {
        float w0 = W[(size_t)(k0 + 2 * q) * H + n];
        float w1 = W[(size_t)(k0 + 2 * q + 1) * H + n];
        u32 h = cvt_bf16x2(w1, w0);
        float e0 = __uint_as_float(h << 16);
        float e1 = __uint_as_float(h & 0xffff0000u);
        hh[q] = h;
        ll[q] = cvt_bf16x2(w1 - e1, w0 - e0);
    }
    g_wth4[dir][idx] = make_uint4(hh[0], hh[1], hh[2], hh[3]);
    g_wtl4[dir][idx] = make_uint4(ll[0], ll[1], ll[2], ll[3]);
}

// ---------------------------------------------------------------------------
// Kernel 1: xw = x @ W + b via HMMA bf16 3-term split; cp.async staging of
// preconverted bf16 tiles, 2-stage double buffer. CTA tile 128m x 128n,
// 8 warps (4M x 2N). Verified swizzle: 16B chunk XOR (kc ^= row&7).
// ---------------------------------------------------------------------------
#define SM_AH 0
#define SM_AL 16384
#define SM_BH 32768
#define SM_BL 49152
#define STG   65536
#define PROJ_SMEM (2 * STG)           // 128KB

__device__ __forceinline__ u32 sw_off(int row, int k) {
    return (u32)(row * 128 + (((k >> 3) ^ (row & 7)) << 4) + (k & 7) * 2);
}

__global__ __launch_bounds__(256) void proj_tc_kernel(
    const float* __restrict__ bfp, const float* __restrict__ bbp)
{
    extern __shared__ char smem[];

    const int dir = blockIdx.z;
    const float* __restrict__ bias = dir ? bbp : bfp;
    float* __restrict__ out = g_xw[dir];
    const uint4* __restrict__ wth = g_wth4[dir];
    const uint4* __restrict__ wtl = g_wtl4[dir];

    const int m0  = blockIdx.x * 128;
    const int n0t = blockIdx.y * 128;

    const int tid  = threadIdx.x;
    const int lane = tid & 31;
    const int wid  = tid >> 5;
    const int gid  = lane >> 2;
    const int tig  = lane & 3;
    const int wm   = wid & 3;
    const int wn   = wid >> 2;
    const int rbase = 32 * wm;
    const int nbase = 64 * wn;

    float acc[2][8][4];
    #pragma unroll
    for (int mf = 0; mf < 2; mf++)
        #pragma unroll
        for (int nf = 0; nf < 8; nf++)
            #pragma unroll
            for (int q = 0; q < 4; q++) acc[mf][nf][q] = 0.f;

    // stage chunk c into buffer s: 1024 (row, kc) 16B chunks per tile
    auto stage = [&](int c, int s) {
        char* base = smem + s * STG;
        #pragma unroll
        for (int i = tid; i < 1024; i += 256) {
            int row = i >> 3, kc = i & 7;
            u32 dst = (u32)(row * 128 + ((kc ^ (row & 7)) << 4));
            size_t srcA = (size_t)(m0 + row) * 32 + c * 8 + kc;
            size_t srcB = (size_t)(n0t + row) * 32 + c * 8 + kc;
            cp_async16(base + SM_AH + dst, &g_xh4[srcA]);
            cp_async16(base + SM_AL + dst, &g_xl4[srcA]);
            cp_async16(base + SM_BH + dst, &wth[srcB]);
            cp_async16(base + SM_BL + dst, &wtl[srcB]);
        }
        asm volatile("cp.async.commit_group;\n");
    };

    stage(0, 0);

    for (int c = 0; c < 4; c++) {
        if (c + 1 < 4) {
            stage(c + 1, (c + 1) & 1);
            asm volatile("cp.async.wait_group 1;\n");
        } else {
            asm volatile("cp.async.wait_group 0;\n");
        }
        __syncthreads();

        const char* sb = smem + (c & 1) * STG;
        #pragma unroll
        for (int ks = 0; ks < 4; ks++) {
            const int k0 = 16 * ks;
            u32 ah[2][4], al[2][4];
            #pragma unroll
            for (int mf = 0; mf < 2; mf++) {
                int r0 = rbase + 16 * mf + gid;
                int r1 = r0 + 8;
                u32 o00 = sw_off(r0, k0 + 2 * tig);
                u32 o10 = sw_off(r1, k0 + 2 * tig);
                u32 o01 = sw_off(r0, k0 + 8 + 2 * tig);
                u32 o11 = sw_off(r1, k0 + 8 + 2 * tig);
                ah[mf][0] = *(const u32*)(sb + SM_AH + o00);
                ah[mf][1] = *(const u32*)(sb + SM_AH + o10);
                ah[mf][2] = *(const u32*)(sb + SM_AH + o01);
                ah[mf][3] = *(const u32*)(sb + SM_AH + o11);
                al[mf][0] = *(const u32*)(sb + SM_AL + o00);
                al[mf][1] = *(const u32*)(sb + SM_AL + o10);
                al[mf][2] = *(const u32*)(sb + SM_AL + o01);
                al[mf][3] = *(const u32*)(sb + SM_AL + o11);
            }
            #pragma unroll
            for (int nf = 0; nf < 8; nf++) {
                int n = nbase + 8 * nf + gid;
                u32 ob0 = sw_off(n, k0 + 2 * tig);
                u32 ob1 = sw_off(n, k0 + 8 + 2 * tig);
                u32 bh0 = *(const u32*)(sb + SM_BH + ob0);
                u32 bh1 = *(const u32*)(sb + SM_BH + ob1);
                u32 bl0 = *(const u32*)(sb + SM_BL + ob0);
                u32 bl1 = *(const u32*)(sb + SM_BL + ob1);
                #pragma unroll
                for (int mf = 0; mf < 2; mf++) {
                    mma_bf16(acc[mf][nf], ah[mf][0], ah[mf][1], ah[mf][2], ah[mf][3], bh0, bh1);
                    mma_bf16(acc[mf][nf], ah[mf][0], ah[mf][1], ah[mf][2], ah[mf][3], bl0, bl1);
                    mma_bf16(acc[mf][nf], al[mf][0], al[mf][1], al[mf][2], al[mf][3], bh0, bh1);
                }
            }
        }
        __syncthreads();
    }

    // epilogue: bias + store
    #pragma unroll
    for (int nf = 0; nf < 8; nf++) {
        int ncol = n0t + nbase + 8 * nf + 2 * tig;
        float2 bv = *(const float2*)&bias[ncol];
        #pragma unroll
        for (int mf = 0; mf < 2; mf++) {
            int row0 = m0 + rbase + 16 * mf + gid;
            int row1 = row0 + 8;
            *(float2*)&out[(size_t)row0 * H + ncol] =
                make_float2(acc[mf][nf][0] + bv.x, acc[mf][nf][1] + bv.y);
            *(float2*)&out[(size_t)row1 * H + ncol] =
                make_float2(acc[mf][nf][2] + bv.x, acc[mf][nf][3] + bv.y);
        }
    }
}

// ---------------------------------------------------------------------------
// Kernel 2: recurrent scan (round-7 version, proven 675us). Unchanged.
// ---------------------------------------------------------------------------
#define NK8 (H / 8)

__global__ __launch_bounds__(256, 1) void scan_kernel(
    const float* __restrict__ Whh_f,
    const float* __restrict__ Whh_b,
    float* __restrict__ out)
{
    __shared__ float hbuf[2 * 2 * H];

    const int blk  = blockIdx.x;
    const int dir  = blk >> 6;
    const int brow = (blk & 63) * 2;
    const float* __restrict__ Whh = dir ? Whh_b : Whh_f;
    const float* __restrict__ xw  = g_xw[dir];
    const int j = threadIdx.x;

    uint4 wreg[NK8];
    #pragma unroll
    for (int k8 = 0; k8 < NK8; k8++) {
        u32 wrd[4];
        #pragma unroll
        for (int q = 0; q < 4; q++) {
            float w0 = Whh[(k8 * 8 + 2 * q)     * H + j];
            float w1 = Whh[(k8 * 8 + 2 * q + 1) * H + j];
            u32 b0 = (u32)__bfloat16_as_ushort(__float2bfloat16(w0));
            u32 b1 = (u32)__bfloat16_as_ushort(__float2bfloat16(w1));
            wrd[q] = (b1 << 16) | b0;
        }
        wreg[k8] = make_uint4(wrd[0], wrd[1], wrd[2], wrd[3]);
    }

    hbuf[j] = 0.f;
    hbuf[H + j] = 0.f;
    __syncthreads();

    float* __restrict__ fin = out + (size_t)T * B * 2 * H;

    int t  = dir ? (T - 1) : 0;
    const int dt = dir ? -1 : 1;
    int p = 0;
    float h0 = 0.f, h1 = 0.f;

    const float* xr = xw + ((size_t)t * B + brow) * H + j;
    float x0 = __ldg(xr);
    float x1 = __ldg(xr + H);

    for (int s = 0; s < T; s++) {
        float xn0 = 0.f, xn1 = 0.f;
        if (s + 1 < T) {
            const float* xr2 = xw + ((size_t)(t + dt) * B + brow) * H + j;
            xn0 = __ldg(xr2);
            xn1 = __ldg(xr2 + H);
        }

        const float* hr0 = hbuf + p * (2 * H);
        const float* hr1 = hr0 + H;

        u64 acc[2][4];
        #pragma unroll
        for (int r = 0; r < 2; r++)
            #pragma unroll
            for (int q = 0; q < 4; q++) acc[r][q] = 0ull;

        #pragma unroll
        for (int k8 = 0; k8 < NK8; k8++) {
            uint4 w = wreg[k8];
            ulonglong2 a0 = *(const ulonglong2*)&hr0[k8 * 8];
            ulonglong2 a1 = *(const ulonglong2*)&hr0[k8 * 8 + 4];
            ulonglong2 b0 = *(const ulonglong2*)&hr1[k8 * 8];
            ulonglong2 b1 = *(const ulonglong2*)&hr1[k8 * 8 + 4];
            u64 w01 = bfpair(w.x);
            u64 w23 = bfpair(w.y);
            u64 w45 = bfpair(w.z);
            u64 w67 = bfpair(w.w);
            ffma2(acc[0][0], a0.x, w01);
            ffma2(acc[0][1], a0.y, w23);
            ffma2(acc[0][2], a1.x, w45);
            ffma2(acc[0][3], a1.y, w67);
            ffma2(acc[1][0], b0.x, w01);
            ffma2(acc[1][1], b0.y, w23);
            ffma2(acc[1][2], b1.x, w45);
            ffma2(acc[1][3], b1.y, w67);
        }

        float lo, hi;
        upk2(lo, hi, acc[0][0]); float s0 = x0 + lo + hi;
        upk2(lo, hi, acc[0][1]); s0 += lo + hi;
        upk2(lo, hi, acc[0][2]); s0 += lo + hi;
        upk2(lo, hi, acc[0][3]); s0 += lo + hi;
        upk2(lo, hi, acc[1][0]); float s1 = x1 + lo + hi;
        upk2(lo, hi, acc[1][1]); s1 += lo + hi;
        upk2(lo, hi, acc[1][2]); s1 += lo + hi;
        upk2(lo, hi, acc[1][3]); s1 += lo + hi;

        h0 = tanh_fast(s0);
        h1 = tanh_fast(s1);

        hbuf[(p ^ 1) * (2 * H) + j]     = h0;
        hbuf[(p ^ 1) * (2 * H) + H + j] = h1;

        size_t ob = ((size_t)t * B + brow) * (2 * H) + (size_t)dir * H + j;
        out[ob]         = h0;
        out[ob + 2 * H] = h1;

        __syncthreads();
        p ^= 1;
        t += dt;
        x0 = xn0;
        x1 = xn1;
    }

    size_t fb = (size_t)dir * B * H + (size_t)brow * H + j;
    fin[fb]     = h0;
    fin[fb + H] = h1;
}

// ---------------------------------------------------------------------------
extern "C" void kernel_launch(void* const* d_in, const int* in_sizes, int n_in,
                              void* d_out, int out_size)
{
    const float* inp = (const float*)d_in[0];
    const float* Wxf = (const float*)d_in[1];
    const float* Whf = (const float*)d_in[2];
    const float* bf  = (const float*)d_in[3];
    const float* Wxb = (const float*)d_in[4];
    const float* Whb = (const float*)d_in[5];
    const float* bb  = (const float*)d_in[6];
    float* out = (float*)d_out;

    cvt_x_kernel<<<TBD / 8 / 256, 256>>>(inp);
    cvt_w_kernel<<<2 * H * (D / 8) / 256, 256>>>(Wxf, Wxb);

    cudaFuncSetAttribute(proj_tc_kernel,
                         cudaFuncAttributeMaxDynamicSharedMemorySize, PROJ_SMEM);
    dim3 g1(T * B / 128, H / 128, 2);
    proj_tc_kernel<<<g1, 256, PROJ_SMEM>>>(bf, bb);

    scan_kernel<<<128, 256>>>(Whf, Whb, out);
}

// round 14
// speedup vs baseline: 2.2817x; 1.1389x over previous
#include <cuda_runtime.h>
#include <cuda_bf16.h>
#include <math.h>

#define T 512
#define B 128
#define D 256
#define H 256
#define TBD (T * B * D)

// Scratch: input projections per direction, bf16 split arrays for proj GEMM.
__device__ float g_xw[2][(size_t)T * B * H];
__device__ uint4 g_xh4[TBD / 8];            // x hi bf16, [m][k] k-major, 8/uint4
__device__ uint4 g_xl4[TBD / 8];            // x lo residual bf16
__device__ uint4 g_wth4[2][H * D / 8];      // W^T hi bf16, [n][k] k-major
__device__ uint4 g_wtl4[2][H * D / 8];      // W^T lo residual

typedef unsigned long long u64;
typedef unsigned int u32;

__device__ __forceinline__ u64 pk2(float lo, float hi) {
    u64 r; asm("mov.b64 %0, {%1, %2};" : "=l"(r) : "f"(lo), "f"(hi)); return r;
}
__device__ __forceinline__ void upk2(float& lo, float& hi, u64 v) {
    asm("mov.b64 {%0, %1}, %2;" : "=f"(lo), "=f"(hi) : "l"(v));
}
__device__ __forceinline__ void ffma2(u64& acc, u64 a, u64 b) {
    asm("fma.rn.f32x2 %0, %1, %2, %3;" : "=l"(acc) : "l"(a), "l"(b), "l"(acc));
}
__device__ __forceinline__ float tanh_fast(float x) {
    float y; asm("tanh.approx.f32 %0, %1;" : "=f"(y) : "f"(x)); return y;
}
__device__ __forceinline__ u64 bfpair(u32 w) {
    u64 r;
    asm("{ .reg .b32 lo, hi;\n"
        "  shl.b32 lo, %1, 16;\n"
        "  and.b32 hi, %1, 0xffff0000;\n"
        "  mov.b64 %0, {lo, hi}; }" : "=l"(r) : "r"(w));
    return r;
}
// pack two f32 into bf16x2: lo16 = cvt(vlo), hi16 = cvt(vhi)
__device__ __forceinline__ u32 cvt_bf16x2(float vhi, float vlo) {
    u32 d; asm("cvt.rn.bf16x2.f32 %0, %1, %2;" : "=r"(d) : "f"(vhi), "f"(vlo));
    return d;
}
__device__ __forceinline__ void cp_async16(void* smem_dst, const void* gptr) {
    u32 saddr = (u32)__cvta_generic_to_shared(smem_dst);
    asm volatile("cp.async.cg.shared.global [%0], [%1], 16;\n" :: "r"(saddr), "l"(gptr));
}

// mma.sync m16n8k16 row.col bf16 -> f32 accum
__device__ __forceinline__ void mma_bf16(float* c, u32 a0, u32 a1, u32 a2, u32 a3,
                                         u32 b0, u32 b1) {
    asm volatile(
        "mma.sync.aligned.m16n8k16.row.col.f32.bf16.bf16.f32 "
        "{%0,%1,%2,%3}, {%4,%5,%6,%7}, {%8,%9}, {%0,%1,%2,%3};"
        : "+f"(c[0]), "+f"(c[1]), "+f"(c[2]), "+f"(c[3])
        : "r"(a0), "r"(a1), "r"(a2), "r"(a3), "r"(b0), "r"(b1));
}

// ---------------------------------------------------------------------------
// Convert kernels (run once, before proj)
// ---------------------------------------------------------------------------
__global__ __launch_bounds__(256) void cvt_x_kernel(const float* __restrict__ inp)
{
    size_t i = (size_t)blockIdx.x * 256 + threadIdx.x;   // over TBD/8
    const float4* p = (const float4*)inp + i * 2;
    float4 v0 = p[0], v1 = p[1];
    u32 h0 = cvt_bf16x2(v0.y, v0.x);
    u32 h1 = cvt_bf16x2(v0.w, v0.z);
    u32 h2 = cvt_bf16x2(v1.y, v1.x);
    u32 h3 = cvt_bf16x2(v1.w, v1.z);
    u32 l0, l1, l2, l3;
    {
        float a0 = __uint_as_float(h0 << 16), a1 = __uint_as_float(h0 & 0xffff0000u);
        l0 = cvt_bf16x2(v0.y - a1, v0.x - a0);
        float b0 = __uint_as_float(h1 << 16), b1 = __uint_as_float(h1 & 0xffff0000u);
        l1 = cvt_bf16x2(v0.w - b1, v0.z - b0);
        float c0 = __uint_as_float(h2 << 16), c1 = __uint_as_float(h2 & 0xffff0000u);
        l2 = cvt_bf16x2(v1.y - c1, v1.x - c0);
        float d0 = __uint_as_float(h3 << 16), d1 = __uint_as_float(h3 & 0xffff0000u);
        l3 = cvt_bf16x2(v1.w - d1, v1.z - d0);
    }
    g_xh4[i] = make_uint4(h0, h1, h2, h3);
    g_xl4[i] = make_uint4(l0, l1, l2, l3);
}

__global__ __launch_bounds__(256) void cvt_w_kernel(const float* __restrict__ Wf,
                                                    const float* __restrict__ Wb)
{
    int i = blockIdx.x * 256 + threadIdx.x;     // over 2 * H * (D/8)
    const int per = H * (D / 8);
    int dir = i / per;
    int idx = i - dir * per;
    int n  = idx >> 5;          // D/8 = 32
    int kc = idx & 31;
    int k0 = kc * 8;
    const float* W = dir ? Wb : Wf;
    u32 hh[4], ll[4];
    #pragma unroll
    for (int q = 0; q < 4; q++) {
        float w0 = W[(size_t)(k0 + 2 * q) * H + n];
        float w1 = W[(size_t)(k0 + 2 * q + 1) * H + n];
        u32 h = cvt_bf16x2(w1, w0);
        float e0 = __uint_as_float(h << 16);
        float e1 = __uint_as_float(h & 0xffff0000u);
        hh[q] = h;
        ll[q] = cvt_bf16x2(w1 - e1, w0 - e0);
    }
    g_wth4[dir][idx] = make_uint4(hh[0], hh[1], hh[2], hh[3]);
    g_wtl4[dir][idx] = make_uint4(ll[0], ll[1], ll[2], ll[3]);
}

// ---------------------------------------------------------------------------
// Kernel 1: xw = x @ W + b via HMMA bf16 3-term split.
// SINGLE 64KB stage -> 2 CTAs/SM; cross-CTA interleaving hides staging.
// CTA tile 128m x 128n, 8 warps (4M x 2N). Verified swizzle layout.
// ---------------------------------------------------------------------------
#define SM_AH 0
#define SM_AL 16384
#define SM_BH 32768
#define SM_BL 49152
#define PROJ_SMEM 65536               // one stage, 64KB

__device__ __forceinline__ u32 sw_off(int row, int k) {
    return (u32)(row * 128 + (((k >> 3) ^ (row & 7)) << 4) + (k & 7) * 2);
}

__global__ __launch_bounds__(256, 2) void proj_tc_kernel(
    const float* __restrict__ bfp, const float* __restrict__ bbp)
{
    extern __shared__ char smem[];

    const int dir = blockIdx.z;
    const float* __restrict__ bias = dir ? bbp : bfp;
    float* __restrict__ out = g_xw[dir];
    const uint4* __restrict__ wth = g_wth4[dir];
    const uint4* __restrict__ wtl = g_wtl4[dir];

    const int m0  = blockIdx.x * 128;
    const int n0t = blockIdx.y * 128;

    const int tid  = threadIdx.x;
    const int lane = tid & 31;
    const int wid  = tid >> 5;
    const int gid  = lane >> 2;
    const int tig  = lane & 3;
    const int wm   = wid & 3;
    const int wn   = wid >> 2;
    const int rbase = 32 * wm;
    const int nbase = 64 * wn;

    float acc[2][8][4];
    #pragma unroll
    for (int mf = 0; mf < 2; mf++)
        #pragma unroll
        for (int nf = 0; nf < 8; nf++)
            #pragma unroll
            for (int q = 0; q < 4; q++) acc[mf][nf][q] = 0.f;

    for (int c = 0; c < 4; c++) {
        __syncthreads();   // previous chunk's math done before overwrite

        // stage chunk c: 1024 (row, kc) 16B chunks per tile
        #pragma unroll
        for (int i = tid; i < 1024; i += 256) {
            int row = i >> 3, kc = i & 7;
            u32 dst = (u32)(row * 128 + ((kc ^ (row & 7)) << 4));
            size_t srcA = (size_t)(m0 + row) * 32 + c * 8 + kc;
            size_t srcB = (size_t)(n0t + row) * 32 + c * 8 + kc;
            cp_async16(smem + SM_AH + dst, &g_xh4[srcA]);
            cp_async16(smem + SM_AL + dst, &g_xl4[srcA]);
            cp_async16(smem + SM_BH + dst, &wth[srcB]);
            cp_async16(smem + SM_BL + dst, &wtl[srcB]);
        }
        asm volatile("cp.async.commit_group;\n");
        asm volatile("cp.async.wait_group 0;\n");
        __syncthreads();

        #pragma unroll
        for (int ks = 0; ks < 4; ks++) {
            const int k0 = 16 * ks;
            u32 ah[2][4], al[2][4];
            #pragma unroll
            for (int mf = 0; mf < 2; mf++) {
                int r0 = rbase + 16 * mf + gid;
                int r1 = r0 + 8;
                u32 o00 = sw_off(r0, k0 + 2 * tig);
                u32 o10 = sw_off(r1, k0 + 2 * tig);
                u32 o01 = sw_off(r0, k0 + 8 + 2 * tig);
                u32 o11 = sw_off(r1, k0 + 8 + 2 * tig);
                ah[mf][0] = *(const u32*)(smem + SM_AH + o00);
                ah[mf][1] = *(const u32*)(smem + SM_AH + o10);
                ah[mf][2] = *(const u32*)(smem + SM_AH + o01);
                ah[mf][3] = *(const u32*)(smem + SM_AH + o11);
                al[mf][0] = *(const u32*)(smem + SM_AL + o00);
                al[mf][1] = *(const u32*)(smem + SM_AL + o10);
                al[mf][2] = *(const u32*)(smem + SM_AL + o01);
                al[mf][3] = *(const u32*)(smem + SM_AL + o11);
            }
            #pragma unroll
            for (int nf = 0; nf < 8; nf++) {
                int n = nbase + 8 * nf + gid;
                u32 ob0 = sw_off(n, k0 + 2 * tig);
                u32 ob1 = sw_off(n, k0 + 8 + 2 * tig);
                u32 bh0 = *(const u32*)(smem + SM_BH + ob0);
                u32 bh1 = *(const u32*)(smem + SM_BH + ob1);
                u32 bl0 = *(const u32*)(smem + SM_BL + ob0);
                u32 bl1 = *(const u32*)(smem + SM_BL + ob1);
                #pragma unroll
                for (int mf = 0; mf < 2; mf++) {
                    mma_bf16(acc[mf][nf], ah[mf][0], ah[mf][1], ah[mf][2], ah[mf][3], bh0, bh1);
                    mma_bf16(acc[mf][nf], ah[mf][0], ah[mf][1], ah[mf][2], ah[mf][3], bl0, bl1);
                    mma_bf16(acc[mf][nf], al[mf][0], al[mf][1], al[mf][2], al[mf][3], bh0, bh1);
                }
            }
        }
    }

    // epilogue: bias + store
    #pragma unroll
    for (int nf = 0; nf < 8; nf++) {
        int ncol = n0t + nbase + 8 * nf + 2 * tig;
        float2 bv = *(const float2*)&bias[ncol];
        #pragma unroll
        for (int mf = 0; mf < 2; mf++) {
            int row0 = m0 + rbase + 16 * mf + gid;
            int row1 = row0 + 8;
            *(float2*)&out[(size_t)row0 * H + ncol] =
                make_float2(acc[mf][nf][0] + bv.x, acc[mf][nf][1] + bv.y);
            *(float2*)&out[(size_t)row1 * H + ncol] =
                make_float2(acc[mf][nf][2] + bv.x, acc[mf][nf][3] + bv.y);
        }
    }
}

// ---------------------------------------------------------------------------
// Kernel 2: recurrent scan (round-7 version, proven). Unchanged.
// ---------------------------------------------------------------------------
#define NK8 (H / 8)

__global__ __launch_bounds__(256, 1) void scan_kernel(
    const float* __restrict__ Whh_f,
    const float* __restrict__ Whh_b,
    float* __restrict__ out)
{
    __shared__ float hbuf[2 * 2 * H];

    const int blk  = blockIdx.x;
    const int dir  = blk >> 6;
    const int brow = (blk & 63) * 2;
    const float* __restrict__ Whh = dir ? Whh_b : Whh_f;
    const float* __restrict__ xw  = g_xw[dir];
    const int j = threadIdx.x;

    uint4 wreg[NK8];
    #pragma unroll
    for (int k8 = 0; k8 < NK8; k8++) {
        u32 wrd[4];
        #pragma unroll
        for (int q = 0; q < 4; q++) {
            float w0 = Whh[(k8 * 8 + 2 * q)     * H + j];
            float w1 = Whh[(k8 * 8 + 2 * q + 1) * H + j];
            u32 b0 = (u32)__bfloat16_as_ushort(__float2bfloat16(w0));
            u32 b1 = (u32)__bfloat16_as_ushort(__float2bfloat16(w1));
            wrd[q] = (b1 << 16) | b0;
        }
        wreg[k8] = make_uint4(wrd[0], wrd[1], wrd[2], wrd[3]);
    }

    hbuf[j] = 0.f;
    hbuf[H + j] = 0.f;
    __syncthreads();

    float* __restrict__ fin = out + (size_t)T * B * 2 * H;

    int t  = dir ? (T - 1) : 0;
    const int dt = dir ? -1 : 1;
    int p = 0;
    float h0 = 0.f, h1 = 0.f;

    const float* xr = xw + ((size_t)t * B + brow) * H + j;
    float x0 = __ldg(xr);
    float x1 = __ldg(xr + H);

    for (int s = 0; s < T; s++) {
        float xn0 = 0.f, xn1 = 0.f;
        if (s + 1 < T) {
            const float* xr2 = xw + ((size_t)(t + dt) * B + brow) * H + j;
            xn0 = __ldg(xr2);
            xn1 = __ldg(xr2 + H);
        }

        const float* hr0 = hbuf + p * (2 * H);
        const float* hr1 = hr0 + H;

        u64 acc[2][4];
        #pragma unroll
        for (int r = 0; r < 2; r++)
            #pragma unroll
            for (int q = 0; q < 4; q++) acc[r][q] = 0ull;

        #pragma unroll
        for (int k8 = 0; k8 < NK8; k8++) {
            uint4 w = wreg[k8];
            ulonglong2 a0 = *(const ulonglong2*)&hr0[k8 * 8];
            ulonglong2 a1 = *(const ulonglong2*)&hr0[k8 * 8 + 4];
            ulonglong2 b0 = *(const ulonglong2*)&hr1[k8 * 8];
            ulonglong2 b1 = *(const ulonglong2*)&hr1[k8 * 8 + 4];
            u64 w01 = bfpair(w.x);
            u64 w23 = bfpair(w.y);
            u64 w45 = bfpair(w.z);
            u64 w67 = bfpair(w.w);
            ffma2(acc[0][0], a0.x, w01);
            ffma2(acc[0][1], a0.y, w23);
            ffma2(acc[0][2], a1.x, w45);
            ffma2(acc[0][3], a1.y, w67);
            ffma2(acc[1][0], b0.x, w01);
            ffma2(acc[1][1], b0.y, w23);
            ffma2(acc[1][2], b1.x, w45);
            ffma2(acc[1][3], b1.y, w67);
        }

        float lo, hi;
        upk2(lo, hi, acc[0][0]); float s0 = x0 + lo + hi;
        upk2(lo, hi, acc[0][1]); s0 += lo + hi;
        upk2(lo, hi, acc[0][2]); s0 += lo + hi;
        upk2(lo, hi, acc[0][3]); s0 += lo + hi;
        upk2(lo, hi, acc[1][0]); float s1 = x1 + lo + hi;
        upk2(lo, hi, acc[1][1]); s1 += lo + hi;
        upk2(lo, hi, acc[1][2]); s1 += lo + hi;
        upk2(lo, hi, acc[1][3]); s1 += lo + hi;

        h0 = tanh_fast(s0);
        h1 = tanh_fast(s1);

        hbuf[(p ^ 1) * (2 * H) + j]     = h0;
        hbuf[(p ^ 1) * (2 * H) + H + j] = h1;

        size_t ob = ((size_t)t * B + brow) * (2 * H) + (size_t)dir * H + j;
        out[ob]         = h0;
        out[ob + 2 * H] = h1;

        __syncthreads();
        p ^= 1;
        t += dt;
        x0 = xn0;
        x1 = xn1;
    }

    size_t fb = (size_t)dir * B * H + (size_t)brow * H + j;
    fin[fb]     = h0;
    fin[fb + H] = h1;
}

// ---------------------------------------------------------------------------
extern "C" void kernel_launch(void* const* d_in, const int* in_sizes, int n_in,
                              void* d_out, int out_size)
{
    const float* inp = (const float*)d_in[0];
    const float* Wxf = (const float*)d_in[1];
    const float* Whf = (const float*)d_in[2];
    const float* bf  = (const float*)d_in[3];
    const float* Wxb = (const float*)d_in[4];
    const float* Whb = (const float*)d_in[5];
    const float* bb  = (const float*)d_in[6];
    float* out = (float*)d_out;

    cvt_x_kernel<<<TBD / 8 / 256, 256>>>(inp);
    cvt_w_kernel<<<2 * H * (D / 8) / 256, 256>>>(Wxf, Wxb);

    cudaFuncSetAttribute(proj_tc_kernel,
                         cudaFuncAttributeMaxDynamicSharedMemorySize, PROJ_SMEM);
    dim3 g1(T * B / 128, H / 128, 2);
    proj_tc_kernel<<<g1, 256, PROJ_SMEM>>>(bf, bb);

    scan_kernel<<<128, 256>>>(Whf, Whb, out);
}